// round 10
// baseline (speedup 1.0000x reference)
#include <cuda_runtime.h>
#include <math.h>

// Problem dims (fixed by the dataset)
#define MB    4
#define TT    2048
#define MR    8192      // B*T
#define DD    1024
#define QKVS  3072      // fused QKV row stride
#define HH    16
#define KK    64
#define BKC   32
#define HK    512       // H*BK
#define FFN_D 4096
#define LORA_R 48

#define THETA_CLIP 1.5707963267948966f

// ---------------- scratch (static device memory; zero-initialized) ------------
__device__ float g_xn  [MR*DD];
__device__ float g_qkv [MR*QKVS];
__device__ float g_wqkv[DD*QKVS];
__device__ float g_bqkv[QKVS];
__device__ float g_t1  [MR*LORA_R];
__device__ float g_zr  [MR*HK];
__device__ float g_zi  [MR*HK];
__device__ float g_y   [MR*DD];
__device__ float g_x1  [MR*DD];
__device__ float g_h2  [MR*DD];
__device__ float g_mid [MR*FFN_D];
__device__ float g_zero[FFN_D];   // stays 0 (used as null bias)

// ---------------- packed fp32x2 helpers (FFMA2 path, sm_100+) -----------------
__device__ __forceinline__ unsigned long long dupf(float x) {
    unsigned long long r; unsigned u = __float_as_uint(x);
    asm("mov.b64 %0, {%1, %1};" : "=l"(r) : "r"(u));
    return r;
}
__device__ __forceinline__ void fma2(unsigned long long& acc,
                                     unsigned long long a, unsigned long long b) {
    asm("fma.rn.f32x2 %0, %1, %2, %0;" : "+l"(acc) : "l"(a), "l"(b));
}
__device__ __forceinline__ void unpack2(unsigned long long p, float& lo, float& hi) {
    asm("mov.b64 {%0, %1}, %2;" : "=f"(lo), "=f"(hi) : "l"(p));
}

// ---------------- QKV weight/bias packing: W = [Wq | Wk | Wv] (D x 3D) --------
__global__ void __launch_bounds__(256) pack_qkv_kernel(
    const float* __restrict__ Wq, const float* __restrict__ Wk,
    const float* __restrict__ Wv, const float* __restrict__ bq,
    const float* __restrict__ bk, const float* __restrict__ bv,
    float* __restrict__ W, float* __restrict__ bias)
{
    int tid = blockIdx.x * 256 + threadIdx.x;   // 0 .. 1024*768-1 (float4 units)
    int d = tid / 768, c = tid % 768;
    const float* src = (c < 256) ? Wq : (c < 512) ? Wk : Wv;
    int cc = c & 255;
    ((float4*)W)[tid] = ((const float4*)(src + (size_t)d * DD))[cc];
    if (tid < 768) {
        const float* sb = (c < 256) ? bq : (c < 512) ? bk : bv;
        ((float4*)bias)[tid] = ((const float4*)sb)[cc];
    }
}

// ---------------- LayerNorm (one block per row, 256 thr, float4) --------------
__global__ void __launch_bounds__(256) ln_kernel(const float* __restrict__ x,
                                                 const float* __restrict__ g,
                                                 const float* __restrict__ b,
                                                 float* __restrict__ out)
{
    __shared__ float red[8];
    int row = blockIdx.x;
    const float4* xr = (const float4*)(x + (size_t)row * DD);
    float4 v = xr[threadIdx.x];

    float s = v.x + v.y + v.z + v.w;
    #pragma unroll
    for (int o = 16; o; o >>= 1) s += __shfl_xor_sync(0xffffffffu, s, o);
    if ((threadIdx.x & 31) == 0) red[threadIdx.x >> 5] = s;
    __syncthreads();
    float tot = 0.f;
    #pragma unroll
    for (int i = 0; i < 8; i++) tot += red[i];
    float mean = tot * (1.f / DD);
    __syncthreads();

    float dx = v.x - mean, dy = v.y - mean, dz = v.z - mean, dw = v.w - mean;
    float ss = dx*dx + dy*dy + dz*dz + dw*dw;
    #pragma unroll
    for (int o = 16; o; o >>= 1) ss += __shfl_xor_sync(0xffffffffu, ss, o);
    if ((threadIdx.x & 31) == 0) red[threadIdx.x >> 5] = ss;
    __syncthreads();
    float tot2 = 0.f;
    #pragma unroll
    for (int i = 0; i < 8; i++) tot2 += red[i];
    float inv = rsqrtf(tot2 * (1.f / DD) + 1e-6f);

    const float4 G = ((const float4*)g)[threadIdx.x];
    const float4 Bv = ((const float4*)b)[threadIdx.x];
    float4 o4;
    o4.x = dx * inv * G.x + Bv.x;
    o4.y = dy * inv * G.y + Bv.y;
    o4.z = dz * inv * G.z + Bv.z;
    o4.w = dw * inv * G.w + Bv.w;
    ((float4*)(out + (size_t)row * DD))[threadIdx.x] = o4;
}

// ---------------- FFMA2 GEMM: C = A(MxK) @ B(KxN) + bias, epilogue ------------
// 256x128 block tile, BK=16, double-buffered smem, 16x8 per thread (as 8x8
// row-pair f32x2 accumulators), 256 threads.
// A smem: [k][row ^ ((k>>2)&3)*8]  (XOR swizzle: conflict-free stores,
//         broadcast-clean b64 row-pair loads)
// EPI: 0 none | 2 tanh | 3 gelu(tanh approx) | 4 add residual
template<int EPI>
__global__ void __launch_bounds__(256, 1)
gemm_kernel(const float* __restrict__ A, const float* __restrict__ B,
            const float* __restrict__ bias, const float* __restrict__ res,
            float* __restrict__ C, int N, int Kd)
{
    __shared__ float As[2][16][256];   // 32 KB
    __shared__ float Bs[2][16][128];   // 16 KB  (total 48 KB)

    const int tid = threadIdx.x;
    const int bm = blockIdx.y * 256, bn = blockIdx.x * 128;

    const int la_r  = tid >> 2;
    const int la_c4 = (tid & 3) * 4;
    const int la_sw = (tid & 3) * 8;
    const int lb_r  = tid >> 4;
    const int lb_c  = (tid & 15) * 4;

    const int tx = (tid & 15) * 8;
    const int ty = (tid >> 4) * 16;

    unsigned long long acc2[8][8];
    #pragma unroll
    for (int i = 0; i < 8; i++)
        #pragma unroll
        for (int j = 0; j < 8; j++) acc2[i][j] = 0ull;

    float4 aR[4]; float4 bR0, bR1;
    const int c0g = bn + lb_c, c1g = c0g + 64;
    const bool bg0 = (c0g + 3) < N;
    const bool bg1 = (c1g + 3) < N;

    // ---- stage 0 ----
    {
        #pragma unroll
        for (int p = 0; p < 4; p++)
            aR[p] = *(const float4*)(A + (size_t)(bm + la_r + p * 64) * Kd + la_c4);
        const float* base = B + (size_t)lb_r * N;
        if (bg0) bR0 = *(const float4*)(base + c0g);
        else {
            bR0.x = (c0g + 0 < N) ? base[c0g + 0] : 0.f;
            bR0.y = (c0g + 1 < N) ? base[c0g + 1] : 0.f;
            bR0.z = (c0g + 2 < N) ? base[c0g + 2] : 0.f;
            bR0.w = (c0g + 3 < N) ? base[c0g + 3] : 0.f;
        }
        if (bg1) bR1 = *(const float4*)(base + c1g);
        else {
            bR1.x = (c1g + 0 < N) ? base[c1g + 0] : 0.f;
            bR1.y = (c1g + 1 < N) ? base[c1g + 1] : 0.f;
            bR1.z = (c1g + 2 < N) ? base[c1g + 2] : 0.f;
            bR1.w = (c1g + 3 < N) ? base[c1g + 3] : 0.f;
        }
    }
    #pragma unroll
    for (int p = 0; p < 4; p++) {
        int r = (la_r + p * 64) ^ la_sw;
        As[0][la_c4 + 0][r] = aR[p].x;
        As[0][la_c4 + 1][r] = aR[p].y;
        As[0][la_c4 + 2][r] = aR[p].z;
        As[0][la_c4 + 3][r] = aR[p].w;
    }
    *(float4*)&Bs[0][lb_r][lb_c]      = bR0;
    *(float4*)&Bs[0][lb_r][lb_c + 64] = bR1;
    __syncthreads();

    int buf = 0;
    for (int k0 = 0; k0 < Kd; k0 += 16) {
        const bool more = (k0 + 16) < Kd;
        if (more) {
            #pragma unroll
            for (int p = 0; p < 4; p++)
                aR[p] = *(const float4*)(A + (size_t)(bm + la_r + p * 64) * Kd + k0 + 16 + la_c4);
            const float* base = B + (size_t)(k0 + 16 + lb_r) * N;
            if (bg0) bR0 = *(const float4*)(base + c0g);
            else {
                bR0.x = (c0g + 0 < N) ? base[c0g + 0] : 0.f;
                bR0.y = (c0g + 1 < N) ? base[c0g + 1] : 0.f;
                bR0.z = (c0g + 2 < N) ? base[c0g + 2] : 0.f;
                bR0.w = (c0g + 3 < N) ? base[c0g + 3] : 0.f;
            }
            if (bg1) bR1 = *(const float4*)(base + c1g);
            else {
                bR1.x = (c1g + 0 < N) ? base[c1g + 0] : 0.f;
                bR1.y = (c1g + 1 < N) ? base[c1g + 1] : 0.f;
                bR1.z = (c1g + 2 < N) ? base[c1g + 2] : 0.f;
                bR1.w = (c1g + 3 < N) ? base[c1g + 3] : 0.f;
            }
        }

        #pragma unroll
        for (int kk = 0; kk < 16; kk++) {
            const float* arow = &As[buf][kk][0];
            const int sw = ((kk >> 2) & 3) * 8;
            unsigned long long av[8];
            #pragma unroll
            for (int ip = 0; ip < 8; ip++)
                av[ip] = *reinterpret_cast<const unsigned long long*>(
                    arow + (((ty + 2 * ip) ^ sw)));
            float4 y0 = *(const float4*)&Bs[buf][kk][tx];
            float4 y1 = *(const float4*)&Bs[buf][kk][tx + 4];
            float bv[8] = {y0.x, y0.y, y0.z, y0.w, y1.x, y1.y, y1.z, y1.w};
            #pragma unroll
            for (int j = 0; j < 8; j++) {
                unsigned long long bd = dupf(bv[j]);
                #pragma unroll
                for (int ip = 0; ip < 8; ip++)
                    fma2(acc2[ip][j], av[ip], bd);
            }
        }

        if (more) {
            int nb = buf ^ 1;
            #pragma unroll
            for (int p = 0; p < 4; p++) {
                int r = (la_r + p * 64) ^ la_sw;
                As[nb][la_c4 + 0][r] = aR[p].x;
                As[nb][la_c4 + 1][r] = aR[p].y;
                As[nb][la_c4 + 2][r] = aR[p].z;
                As[nb][la_c4 + 3][r] = aR[p].w;
            }
            *(float4*)&Bs[nb][lb_r][lb_c]      = bR0;
            *(float4*)&Bs[nb][lb_r][lb_c + 64] = bR1;
            __syncthreads();
            buf = nb;
        }
    }

    // ---- epilogue ----
    float bcol[8];
    #pragma unroll
    for (int j = 0; j < 8; j++) {
        int c = bn + tx + j;
        bcol[j] = (c < N) ? bias[c] : 0.f;
    }
    const bool colvec = (bn + tx + 7) < N;

    #pragma unroll
    for (int ip = 0; ip < 8; ip++) {
        float v0[8], v1[8];
        #pragma unroll
        for (int j = 0; j < 8; j++) unpack2(acc2[ip][j], v0[j], v1[j]);
        int r0 = bm + ty + 2 * ip;
        #pragma unroll
        for (int half = 0; half < 2; half++) {
            float* vv = half ? v1 : v0;
            int row = r0 + half;
            float* crow = C + (size_t)row * N;
            const float* rrow = (EPI == 4) ? (res + (size_t)row * N) : (const float*)0;
            float ov[8];
            #pragma unroll
            for (int j = 0; j < 8; j++) {
                float val = vv[j] + bcol[j];
                if (EPI == 2) val = tanhf(val);
                else if (EPI == 3) {
                    float u = val;
                    float t = tanhf(0.7978845608028654f * (u + 0.044715f * u * u * u));
                    val = 0.5f * u * (1.f + t);
                }
                ov[j] = val;
            }
            if (colvec) {
                if (EPI == 4) {
                    float4 rA = *(const float4*)(rrow + bn + tx);
                    float4 rB = *(const float4*)(rrow + bn + tx + 4);
                    ov[0] += rA.x; ov[1] += rA.y; ov[2] += rA.z; ov[3] += rA.w;
                    ov[4] += rB.x; ov[5] += rB.y; ov[6] += rB.z; ov[7] += rB.w;
                }
                float4 s0 = {ov[0], ov[1], ov[2], ov[3]};
                float4 s1 = {ov[4], ov[5], ov[6], ov[7]};
                *(float4*)(crow + bn + tx)     = s0;
                *(float4*)(crow + bn + tx + 4) = s1;
            } else {
                #pragma unroll
                for (int j = 0; j < 8; j++) {
                    int c = bn + tx + j;
                    if (c < N) {
                        float val = ov[j];
                        if (EPI == 4) val += rrow[c];
                        crow[c] = val;
                    }
                }
            }
        }
    }
}

// ---------------- LoRA second matmul + per-step decay z = exp(-lam + i*theta) -
__global__ void __launch_bounds__(512) z_kernel(const float* __restrict__ t1,
                                                const float* __restrict__ W2,
                                                const float* __restrict__ tb,
                                                const float* __restrict__ lb,
                                                const float* __restrict__ eta,
                                                float* __restrict__ zr,
                                                float* __restrict__ zi)
{
    __shared__ float s1[LORA_R];
    int row = blockIdx.x;
    int c = threadIdx.x;
    if (c < LORA_R) s1[c] = t1[(size_t)row * LORA_R + c];
    __syncthreads();

    float acc = 0.f;
    #pragma unroll
    for (int l = 0; l < LORA_R; l++) acc += s1[l] * W2[l * HK + c];

    float th = tb[c] + acc;
    th = fminf(fmaxf(th, -THETA_CLIP), THETA_CLIP);
    float lam = lb[c] + eta[c] * th * th;
    float e = expf(-lam);
    float sn, cs;
    sincosf(th, &sn, &cs);
    zr[(size_t)row * HK + c] = e * cs;
    zi[(size_t)row * HK + c] = e * sn;
}

// ---------------- Sequential linear-attention scan ----------------------------
// Reads fused qkv buffer (stride QKVS; q at +0, k at +1024, v at +2048).
// phi(k) = elu(k)+1 applied when staging k into smem.
// Recurrence per (b,h,bk,k):  S = z*S + phi_k_c*v ;  y[t][k] = sum_bk Re(conj(q)*S)
// Independent across k -> split k over KSPLIT blocks per (b,h).
// Block: 1024 threads; lane = bk (0..31), warp w = local k index (0..31).
#define KSPLIT 2
__global__ void __launch_bounds__(1024) scan_kernel(const float* __restrict__ qkv,
                                                    const float* __restrict__ zr,
                                                    const float* __restrict__ zi,
                                                    float* __restrict__ y)
{
    __shared__ float sq[8][64], sk[8][64], sv[8][32];
    __shared__ float szr[8][32], szi[8][32];

    int blk = blockIdx.x;
    int ks  = blk & (KSPLIT - 1);        // which 32-wide k slice
    int bh  = blk / KSPLIT;
    int b = bh >> 4, h = bh & 15;
    int tid = threadIdx.x;
    int lane = tid & 31;   // bk
    int w = tid >> 5;      // local k (0..31)
    int kofs = ks * 32;

    size_t baseA = ((size_t)b * TT) * QKVS + h * KK;   // q; k at +DD, v at +2*DD
    size_t baseY = ((size_t)b * TT) * DD   + h * KK;
    size_t baseZ = ((size_t)b * TT) * HK   + h * BKC;

    float Sr = 0.f, Si = 0.f;

    for (int t0 = 0; t0 < TT; t0 += 8) {
        __syncthreads();
        #pragma unroll
        for (int i = tid; i < 1792; i += 1024) {
            if (i < 512) {
                int st = i >> 6, c = i & 63;
                sq[st][c] = qkv[baseA + (size_t)(t0 + st) * QKVS + c];
            } else if (i < 1024) {
                int j = i - 512; int st = j >> 6, c = j & 63;
                float kv = qkv[baseA + (size_t)(t0 + st) * QKVS + DD + c];
                sk[st][c] = (kv > 0.f) ? (kv + 1.f) : expf(kv);   // phi = elu+1
            } else if (i < 1280) {
                int j = i - 1024; int st = j >> 5, c = j & 31;
                sv[st][c] = qkv[baseA + (size_t)(t0 + st) * QKVS + 2 * DD + kofs + c];
            } else if (i < 1536) {
                int j = i - 1280; int st = j >> 5, c = j & 31;
                szr[st][c] = zr[baseZ + (size_t)(t0 + st) * HK + c];
            } else {
                int j = i - 1536; int st = j >> 5, c = j & 31;
                szi[st][c] = zi[baseZ + (size_t)(t0 + st) * HK + c];
            }
        }
        __syncthreads();

        #pragma unroll
        for (int s = 0; s < 8; s++) {
            float2 qc = *(float2*)&sq[s][2 * lane];
            float2 kc = *(float2*)&sk[s][2 * lane];
            float vv = sv[s][w];
            float a = szr[s][lane], bb = szi[s][lane];

            float nr = a * Sr - bb * Si + kc.x * vv;
            float ni = a * Si + bb * Sr + kc.y * vv;
            Sr = nr; Si = ni;

            float y0 = qc.x * Sr + qc.y * Si;   // Re(conj(q) * S)
            #pragma unroll
            for (int o = 16; o; o >>= 1)
                y0 += __shfl_xor_sync(0xffffffffu, y0, o);
            if (lane == 0)
                y[baseY + (size_t)(t0 + s) * DD + kofs + w] = y0;
        }
    }
}

// ---------------- host launcher ----------------------------------------------
static float* sym(const void* s) {
    void* p = nullptr;
    cudaGetSymbolAddress(&p, s);
    return (float*)p;
}

extern "C" void kernel_launch(void* const* d_in, const int* in_sizes, int n_in,
                              void* d_out, int out_size)
{
    const float* x   = (const float*)d_in[0];
    const float* Wq  = (const float*)d_in[1];
    const float* bq  = (const float*)d_in[2];
    const float* Wk  = (const float*)d_in[3];
    const float* bk  = (const float*)d_in[4];
    const float* Wv  = (const float*)d_in[5];
    const float* bv  = (const float*)d_in[6];
    const float* Wo  = (const float*)d_in[7];
    const float* bo  = (const float*)d_in[8];
    const float* n1g = (const float*)d_in[9];
    const float* n1b = (const float*)d_in[10];
    const float* n2g = (const float*)d_in[11];
    const float* n2b = (const float*)d_in[12];
    const float* tb  = (const float*)d_in[13];
    const float* tw1 = (const float*)d_in[14];
    const float* tw2 = (const float*)d_in[15];
    const float* lb  = (const float*)d_in[16];
    const float* eta = (const float*)d_in[17];
    const float* Wf1 = (const float*)d_in[18];
    const float* bf1 = (const float*)d_in[19];
    const float* Wf2 = (const float*)d_in[20];
    const float* bf2 = (const float*)d_in[21];
    float* out = (float*)d_out;

    float* xn   = sym(g_xn);
    float* qkv  = sym(g_qkv);
    float* wqkv = sym(g_wqkv);
    float* bqkv = sym(g_bqkv);
    float* t1   = sym(g_t1);
    float* zr   = sym(g_zr);
    float* zi   = sym(g_zi);
    float* yb   = sym(g_y);
    float* x1   = sym(g_x1);
    float* h2   = sym(g_h2);
    float* mid  = sym(g_mid);
    float* zero = sym(g_zero);

    dim3 gemm_threads(256);
    dim3 grid_d(DD / 128, MR / 256);      // N=1024
    dim3 grid_q(QKVS / 128, MR / 256);    // N=3072 fused QKV
    dim3 grid_f(FFN_D / 128, MR / 256);   // N=4096
    dim3 grid_l(1, MR / 256);             // N=48 (guarded)

    // 0. pack QKV weights/biases
    pack_qkv_kernel<<<DD * 768 / 256, 256>>>(Wq, Wk, Wv, bq, bk, bv, wqkv, bqkv);
    // 1. LN1
    ln_kernel<<<MR, 256>>>(x, n1g, n1b, xn);
    // 2. fused QKV projection
    gemm_kernel<0><<<grid_q, gemm_threads>>>(xn, wqkv, bqkv, nullptr, qkv, QKVS, DD);
    // 3. LoRA stage 1: tanh(xn @ theta_w1)
    gemm_kernel<2><<<grid_l, gemm_threads>>>(xn, tw1, zero, nullptr, t1, LORA_R, DD);
    // 4. LoRA stage 2 + theta/lambda -> per-step complex decay z
    z_kernel<<<MR, 512>>>(t1, tw2, tb, lb, eta, zr, zi);
    // 5. causal linear attention scan (phi applied inline; k split over KSPLIT)
    scan_kernel<<<MB * HH * KSPLIT, 1024>>>(qkv, zr, zi, yb);
    // 6. output projection + residual
    gemm_kernel<4><<<grid_d, gemm_threads>>>(yb, Wo, bo, x, x1, DD, DD);
    // 7. LN2
    ln_kernel<<<MR, 256>>>(x1, n2g, n2b, h2);
    // 8. FFN up + gelu
    gemm_kernel<3><<<grid_f, gemm_threads>>>(h2, Wf1, bf1, nullptr, mid, FFN_D, DD);
    // 9. FFN down + residual -> out
    gemm_kernel<4><<<grid_d, gemm_threads>>>(mid, Wf2, bf2, x1, out, DD, FFN_D);
}

// round 13
// speedup vs baseline: 1.3791x; 1.3791x over previous
#include <cuda_runtime.h>
#include <cuda_bf16.h>
#include <math.h>
#include <stdint.h>

// Problem dims (fixed by the dataset)
#define MB    4
#define TT    2048
#define MR    8192      // B*T
#define DD    1024
#define QKVS  3072      // fused QKV row stride
#define HH    16
#define KK    64
#define BKC   32
#define HK    512       // H*BK
#define FFN_D 4096
#define LORA_R 48
#define LORA_P 128      // padded LoRA width

#define THETA_CLIP 1.5707963267948966f

// ---------------- scratch (static device memory; zero-initialized) ------------
__device__ float g_qkv [MR*QKVS];
__device__ float g_bqkv[QKVS];
__device__ float g_t1  [MR*LORA_P];
__device__ float g_zr  [MR*HK];
__device__ float g_zi  [MR*HK];
__device__ float g_x1  [MR*DD];
__device__ float g_zero[FFN_D];   // stays 0 (null bias)

// bf16 hi/lo activation buffers (A operands, [M x K] k-major)
__device__ __nv_bfloat16 g_xnh[MR*DD],   g_xnl[MR*DD];
__device__ __nv_bfloat16 g_ybh[MR*DD],   g_ybl[MR*DD];
__device__ __nv_bfloat16 g_h2h[MR*DD],   g_h2l[MR*DD];
__device__ __nv_bfloat16 g_midh[MR*FFN_D], g_midl[MR*FFN_D];

// bf16 transposed weights (hi/lo split), [N x K] K-major
__device__ __nv_bfloat16 g_btq_h[QKVS*DD],  g_btq_l[QKVS*DD];
__device__ __nv_bfloat16 g_bto_h[DD*DD],    g_bto_l[DD*DD];
__device__ __nv_bfloat16 g_bf1_h[FFN_D*DD], g_bf1_l[FFN_D*DD];
__device__ __nv_bfloat16 g_bf2_h[DD*FFN_D], g_bf2_l[DD*FFN_D];
__device__ __nv_bfloat16 g_btl_h[LORA_P*DD],g_btl_l[LORA_P*DD];

// ---------------- helpers -----------------------------------------------------
__device__ __forceinline__ void bsplit(float v, __nv_bfloat16& h, __nv_bfloat16& l) {
    h = __float2bfloat16_rn(v);
    l = __float2bfloat16_rn(v - __bfloat162float(h));
}

#define MMA_BF16(c, a, b0, b1) \
    asm volatile("mma.sync.aligned.m16n8k16.row.col.f32.bf16.bf16.f32 " \
        "{%0,%1,%2,%3}, {%4,%5,%6,%7}, {%8,%9}, {%0,%1,%2,%3};" \
        : "+f"((c)[0]), "+f"((c)[1]), "+f"((c)[2]), "+f"((c)[3]) \
        : "r"((a)[0]), "r"((a)[1]), "r"((a)[2]), "r"((a)[3]), "r"(b0), "r"(b1))

// ---------------- transpose+convert: W[K x Nsrc] fp32 -> [Ndst x K] bf16 hi/lo -
__global__ void __launch_bounds__(256) tconv_kernel(const float* __restrict__ W,
                                                    __nv_bfloat16* __restrict__ Bh,
                                                    __nv_bfloat16* __restrict__ Bl,
                                                    int Kd, int Nsrc)
{
    __shared__ float tile[32][33];
    int nb = blockIdx.x * 32, kb = blockIdx.y * 32;
    int tx = threadIdx.x & 31, ty = threadIdx.x >> 5;
    for (int i = ty; i < 32; i += 8) {
        int n = nb + tx;
        tile[i][tx] = (n < Nsrc) ? W[(size_t)(kb + i) * Nsrc + n] : 0.f;
    }
    __syncthreads();
    int nl = threadIdx.x >> 3, kl = (threadIdx.x & 7) * 4;
    size_t base = (size_t)(nb + nl) * Kd + kb + kl;
    #pragma unroll
    for (int j = 0; j < 4; j++) {
        float x = tile[kl + j][nl];
        __nv_bfloat16 h, l;
        bsplit(x, h, l);
        Bh[base + j] = h;
        Bl[base + j] = l;
    }
}

// ---------------- QKV bias pack -----------------------------------------------
__global__ void __launch_bounds__(256) pack_bias_kernel(const float* __restrict__ bq,
                                                        const float* __restrict__ bk,
                                                        const float* __restrict__ bv,
                                                        float* __restrict__ bias)
{
    int t = blockIdx.x * 256 + threadIdx.x;
    bias[t] = (t < 1024) ? bq[t] : (t < 2048) ? bk[t - 1024] : bv[t - 2048];
}

// ---------------- LayerNorm -> bf16 hi/lo outputs ------------------------------
__global__ void __launch_bounds__(256) ln_kernel(const float* __restrict__ x,
                                                 const float* __restrict__ g,
                                                 const float* __restrict__ b,
                                                 __nv_bfloat16* __restrict__ oh,
                                                 __nv_bfloat16* __restrict__ ol)
{
    __shared__ float red[8];
    int row = blockIdx.x;
    const float4* xr = (const float4*)(x + (size_t)row * DD);
    float4 v = xr[threadIdx.x];

    float s = v.x + v.y + v.z + v.w;
    #pragma unroll
    for (int o = 16; o; o >>= 1) s += __shfl_xor_sync(0xffffffffu, s, o);
    if ((threadIdx.x & 31) == 0) red[threadIdx.x >> 5] = s;
    __syncthreads();
    float tot = 0.f;
    #pragma unroll
    for (int i = 0; i < 8; i++) tot += red[i];
    float mean = tot * (1.f / DD);
    __syncthreads();

    float dx = v.x - mean, dy = v.y - mean, dz = v.z - mean, dw = v.w - mean;
    float ss = dx*dx + dy*dy + dz*dz + dw*dw;
    #pragma unroll
    for (int o = 16; o; o >>= 1) ss += __shfl_xor_sync(0xffffffffu, ss, o);
    if ((threadIdx.x & 31) == 0) red[threadIdx.x >> 5] = ss;
    __syncthreads();
    float tot2 = 0.f;
    #pragma unroll
    for (int i = 0; i < 8; i++) tot2 += red[i];
    float inv = rsqrtf(tot2 * (1.f / DD) + 1e-6f);

    const float4 G = ((const float4*)g)[threadIdx.x];
    const float4 Bv = ((const float4*)b)[threadIdx.x];
    float o0 = dx * inv * G.x + Bv.x;
    float o1 = dy * inv * G.y + Bv.y;
    float o2 = dz * inv * G.z + Bv.z;
    float o3 = dw * inv * G.w + Bv.w;

    __nv_bfloat16 h0, l0, h1, l1, h2, l2, h3, l3;
    bsplit(o0, h0, l0); bsplit(o1, h1, l1);
    bsplit(o2, h2, l2); bsplit(o3, h3, l3);
    size_t base = (size_t)row * DD + threadIdx.x * 4;
    *(__nv_bfloat162*)(oh + base)     = __nv_bfloat162(h0, h1);
    *(__nv_bfloat162*)(oh + base + 2) = __nv_bfloat162(h2, h3);
    *(__nv_bfloat162*)(ol + base)     = __nv_bfloat162(l0, l1);
    *(__nv_bfloat162*)(ol + base + 2) = __nv_bfloat162(l2, l3);
}

// ---------------- HMMA bf16-split GEMM ----------------------------------------
// C[M x N] = A(hi+lo)[M x Kd] @ Bt(hi+lo)[N x Kd]^T + bias, epilogue.
// 3 products: Ah*Bh + Ah*Bl + Al*Bh.  Tile 128x128, BK=32, 8 warps (4M x 2N),
// warp tile 32x64 = 2 m16 x 8 n8 frags, mma.sync m16n8k16.
// EPI: 0 none | 2 tanh | 3 gelu | 4 residual.  OUTB: 0 fp32 C | 1 bf16 hi/lo.
#define SROW 40   // smem row stride in bf16 (80B = 20 banks: conflict-free frags)

template<int EPI, int OUTB>
__global__ void __launch_bounds__(256)
tgemm_kernel(const __nv_bfloat16* __restrict__ Agh,
             const __nv_bfloat16* __restrict__ Agl,
             const __nv_bfloat16* __restrict__ Bgh,
             const __nv_bfloat16* __restrict__ Bgl,
             const float* __restrict__ bias,
             const float* __restrict__ res,
             float* __restrict__ C,
             __nv_bfloat16* __restrict__ Ch,
             __nv_bfloat16* __restrict__ Cl,
             int N, int Kd)
{
    __shared__ __align__(16) __nv_bfloat16 sAh[128 * SROW];
    __shared__ __align__(16) __nv_bfloat16 sAl[128 * SROW];
    __shared__ __align__(16) __nv_bfloat16 sBh[128 * SROW];
    __shared__ __align__(16) __nv_bfloat16 sBl[128 * SROW];

    const int tid = threadIdx.x;
    const int lane = tid & 31, wid = tid >> 5;
    const int gp = lane >> 2, tg = lane & 3;
    const int wm = wid & 3, wn = wid >> 2;
    const int bm = blockIdx.y * 128, bn = blockIdx.x * 128;

    float acc[2][8][4];
    #pragma unroll
    for (int mt = 0; mt < 2; mt++)
        #pragma unroll
        for (int nt = 0; nt < 8; nt++)
            #pragma unroll
            for (int j = 0; j < 4; j++) acc[mt][nt][j] = 0.f;

    for (int k0 = 0; k0 < Kd; k0 += 32) {
        __syncthreads();
        // stage: 128 rows x 32 bf16 per tile; (row, q) pairs, q = 8-elem chunk
        #pragma unroll
        for (int p = 0; p < 2; p++) {
            int idx = p * 256 + tid;
            int row = idx >> 2, q = idx & 3;
            size_t ga = (size_t)(bm + row) * Kd + k0 + q * 8;
            size_t gb = (size_t)(bn + row) * Kd + k0 + q * 8;
            int so = row * SROW + q * 8;
            *(uint4*)&sAh[so] = *(const uint4*)(Agh + ga);
            *(uint4*)&sAl[so] = *(const uint4*)(Agl + ga);
            *(uint4*)&sBh[so] = *(const uint4*)(Bgh + gb);
            *(uint4*)&sBl[so] = *(const uint4*)(Bgl + gb);
        }
        __syncthreads();

        #pragma unroll
        for (int ks = 0; ks < 32; ks += 16) {
            uint32_t ah[2][4], al[2][4];
            #pragma unroll
            for (int mt = 0; mt < 2; mt++) {
                int base = (wm * 32 + mt * 16 + gp) * SROW + ks + tg * 2;
                ah[mt][0] = *(uint32_t*)&sAh[base];
                ah[mt][1] = *(uint32_t*)&sAh[base + 8 * SROW];
                ah[mt][2] = *(uint32_t*)&sAh[base + 8];
                ah[mt][3] = *(uint32_t*)&sAh[base + 8 * SROW + 8];
                al[mt][0] = *(uint32_t*)&sAl[base];
                al[mt][1] = *(uint32_t*)&sAl[base + 8 * SROW];
                al[mt][2] = *(uint32_t*)&sAl[base + 8];
                al[mt][3] = *(uint32_t*)&sAl[base + 8 * SROW + 8];
            }
            #pragma unroll
            for (int nt = 0; nt < 8; nt++) {
                int bbase = (wn * 64 + nt * 8 + gp) * SROW + ks + tg * 2;
                uint32_t bh0 = *(uint32_t*)&sBh[bbase];
                uint32_t bh1 = *(uint32_t*)&sBh[bbase + 8];
                uint32_t bl0 = *(uint32_t*)&sBl[bbase];
                uint32_t bl1 = *(uint32_t*)&sBl[bbase + 8];
                #pragma unroll
                for (int mt = 0; mt < 2; mt++) {
                    MMA_BF16(acc[mt][nt], ah[mt], bh0, bh1);
                    MMA_BF16(acc[mt][nt], ah[mt], bl0, bl1);
                    MMA_BF16(acc[mt][nt], al[mt], bh0, bh1);
                }
            }
        }
    }

    // ---- epilogue ----
    #pragma unroll
    for (int mt = 0; mt < 2; mt++) {
        #pragma unroll
        for (int nt = 0; nt < 8; nt++) {
            int m0 = bm + wm * 32 + mt * 16 + gp;
            int n0 = bn + wn * 64 + nt * 8 + tg * 2;
            float2 bb = *(const float2*)(bias + n0);
            #pragma unroll
            for (int half = 0; half < 2; half++) {
                int m = m0 + half * 8;
                float v0 = acc[mt][nt][half * 2 + 0] + bb.x;
                float v1 = acc[mt][nt][half * 2 + 1] + bb.y;
                if (EPI == 2) { v0 = tanhf(v0); v1 = tanhf(v1); }
                else if (EPI == 3) {
                    float t0 = tanhf(0.7978845608028654f * (v0 + 0.044715f * v0 * v0 * v0));
                    float t1 = tanhf(0.7978845608028654f * (v1 + 0.044715f * v1 * v1 * v1));
                    v0 = 0.5f * v0 * (1.f + t0);
                    v1 = 0.5f * v1 * (1.f + t1);
                } else if (EPI == 4) {
                    float2 rr = *(const float2*)(res + (size_t)m * N + n0);
                    v0 += rr.x; v1 += rr.y;
                }
                if (OUTB) {
                    __nv_bfloat16 h0, l0, h1, l1;
                    bsplit(v0, h0, l0); bsplit(v1, h1, l1);
                    *(__nv_bfloat162*)(Ch + (size_t)m * N + n0) = __nv_bfloat162(h0, h1);
                    *(__nv_bfloat162*)(Cl + (size_t)m * N + n0) = __nv_bfloat162(l0, l1);
                } else {
                    float2 o = {v0, v1};
                    *(float2*)(C + (size_t)m * N + n0) = o;
                }
            }
        }
    }
}

// ---------------- LoRA stage 2 + decay z = exp(-lam + i*theta) ----------------
__global__ void __launch_bounds__(512) z_kernel(const float* __restrict__ t1,
                                                const float* __restrict__ W2,
                                                const float* __restrict__ tb,
                                                const float* __restrict__ lb,
                                                const float* __restrict__ eta,
                                                float* __restrict__ zr,
                                                float* __restrict__ zi)
{
    __shared__ float s1[LORA_R];
    int row = blockIdx.x;
    int c = threadIdx.x;
    if (c < LORA_R) s1[c] = t1[(size_t)row * LORA_P + c];
    __syncthreads();

    float acc = 0.f;
    #pragma unroll
    for (int l = 0; l < LORA_R; l++) acc += s1[l] * W2[l * HK + c];

    float th = tb[c] + acc;
    th = fminf(fmaxf(th, -THETA_CLIP), THETA_CLIP);
    float lam = lb[c] + eta[c] * th * th;
    float e = expf(-lam);
    float sn, cs;
    sincosf(th, &sn, &cs);
    zr[(size_t)row * HK + c] = e * cs;
    zi[(size_t)row * HK + c] = e * sn;
}

// ---------------- Sequential linear-attention scan ----------------------------
// Writes y as bf16 hi/lo (A operand of Wo GEMM).
#define KSPLIT 2
__global__ void __launch_bounds__(1024) scan_kernel(const float* __restrict__ qkv,
                                                    const float* __restrict__ zr,
                                                    const float* __restrict__ zi,
                                                    __nv_bfloat16* __restrict__ yh,
                                                    __nv_bfloat16* __restrict__ yl)
{
    __shared__ float sq[8][64], sk[8][64], sv[8][32];
    __shared__ float szr[8][32], szi[8][32];

    int blk = blockIdx.x;
    int ks  = blk & (KSPLIT - 1);
    int bh  = blk / KSPLIT;
    int b = bh >> 4, h = bh & 15;
    int tid = threadIdx.x;
    int lane = tid & 31;
    int w = tid >> 5;
    int kofs = ks * 32;

    size_t baseA = ((size_t)b * TT) * QKVS + h * KK;
    size_t baseY = ((size_t)b * TT) * DD   + h * KK;
    size_t baseZ = ((size_t)b * TT) * HK   + h * BKC;

    float Sr = 0.f, Si = 0.f;

    for (int t0 = 0; t0 < TT; t0 += 8) {
        __syncthreads();
        #pragma unroll
        for (int i = tid; i < 1792; i += 1024) {
            if (i < 512) {
                int st = i >> 6, c = i & 63;
                sq[st][c] = qkv[baseA + (size_t)(t0 + st) * QKVS + c];
            } else if (i < 1024) {
                int j = i - 512; int st = j >> 6, c = j & 63;
                float kv = qkv[baseA + (size_t)(t0 + st) * QKVS + DD + c];
                sk[st][c] = (kv > 0.f) ? (kv + 1.f) : expf(kv);
            } else if (i < 1280) {
                int j = i - 1024; int st = j >> 5, c = j & 31;
                sv[st][c] = qkv[baseA + (size_t)(t0 + st) * QKVS + 2 * DD + kofs + c];
            } else if (i < 1536) {
                int j = i - 1280; int st = j >> 5, c = j & 31;
                szr[st][c] = zr[baseZ + (size_t)(t0 + st) * HK + c];
            } else {
                int j = i - 1536; int st = j >> 5, c = j & 31;
                szi[st][c] = zi[baseZ + (size_t)(t0 + st) * HK + c];
            }
        }
        __syncthreads();

        #pragma unroll
        for (int s = 0; s < 8; s++) {
            float2 qc = *(float2*)&sq[s][2 * lane];
            float2 kc = *(float2*)&sk[s][2 * lane];
            float vv = sv[s][w];
            float a = szr[s][lane], bb = szi[s][lane];

            float nr = a * Sr - bb * Si + kc.x * vv;
            float ni = a * Si + bb * Sr + kc.y * vv;
            Sr = nr; Si = ni;

            float y0 = qc.x * Sr + qc.y * Si;
            #pragma unroll
            for (int o = 16; o; o >>= 1)
                y0 += __shfl_xor_sync(0xffffffffu, y0, o);
            if (lane == 0) {
                __nv_bfloat16 hh, ll;
                bsplit(y0, hh, ll);
                size_t idx = baseY + (size_t)(t0 + s) * DD + kofs + w;
                yh[idx] = hh;
                yl[idx] = ll;
            }
        }
    }
}

// ---------------- host launcher ----------------------------------------------
static float* sym(const void* s) {
    void* p = nullptr;
    cudaGetSymbolAddress(&p, s);
    return (float*)p;
}
static __nv_bfloat16* symb(const void* s) {
    void* p = nullptr;
    cudaGetSymbolAddress(&p, s);
    return (__nv_bfloat16*)p;
}

extern "C" void kernel_launch(void* const* d_in, const int* in_sizes, int n_in,
                              void* d_out, int out_size)
{
    const float* x   = (const float*)d_in[0];
    const float* Wq  = (const float*)d_in[1];
    const float* bq  = (const float*)d_in[2];
    const float* Wk  = (const float*)d_in[3];
    const float* bk  = (const float*)d_in[4];
    const float* Wv  = (const float*)d_in[5];
    const float* bv  = (const float*)d_in[6];
    const float* Wo  = (const float*)d_in[7];
    const float* bo  = (const float*)d_in[8];
    const float* n1g = (const float*)d_in[9];
    const float* n1b = (const float*)d_in[10];
    const float* n2g = (const float*)d_in[11];
    const float* n2b = (const float*)d_in[12];
    const float* tb  = (const float*)d_in[13];
    const float* tw1 = (const float*)d_in[14];
    const float* tw2 = (const float*)d_in[15];
    const float* lb  = (const float*)d_in[16];
    const float* eta = (const float*)d_in[17];
    const float* Wf1 = (const float*)d_in[18];
    const float* bf1 = (const float*)d_in[19];
    const float* Wf2 = (const float*)d_in[20];
    const float* bf2 = (const float*)d_in[21];
    float* out = (float*)d_out;

    float* qkv  = sym(g_qkv);
    float* bqkv = sym(g_bqkv);
    float* t1   = sym(g_t1);
    float* zr   = sym(g_zr);
    float* zi   = sym(g_zi);
    float* x1   = sym(g_x1);
    float* zero = sym(g_zero);

    __nv_bfloat16 *xnh = symb(g_xnh), *xnl = symb(g_xnl);
    __nv_bfloat16 *ybh = symb(g_ybh), *ybl = symb(g_ybl);
    __nv_bfloat16 *h2h = symb(g_h2h), *h2l = symb(g_h2l);
    __nv_bfloat16 *midh = symb(g_midh), *midl = symb(g_midl);
    __nv_bfloat16 *btq_h = symb(g_btq_h), *btq_l = symb(g_btq_l);
    __nv_bfloat16 *bto_h = symb(g_bto_h), *bto_l = symb(g_bto_l);
    __nv_bfloat16 *bf1_h = symb(g_bf1_h), *bf1_l = symb(g_bf1_l);
    __nv_bfloat16 *bf2_h = symb(g_bf2_h), *bf2_l = symb(g_bf2_l);
    __nv_bfloat16 *btl_h = symb(g_btl_h), *btl_l = symb(g_btl_l);

    // 0. weight transpose + bf16 hi/lo split
    tconv_kernel<<<dim3(32, 32), 256>>>(Wq, btq_h, btq_l, DD, DD);
    tconv_kernel<<<dim3(32, 32), 256>>>(Wk, btq_h + (size_t)DD * DD, btq_l + (size_t)DD * DD, DD, DD);
    tconv_kernel<<<dim3(32, 32), 256>>>(Wv, btq_h + (size_t)2 * DD * DD, btq_l + (size_t)2 * DD * DD, DD, DD);
    tconv_kernel<<<dim3(32, 32), 256>>>(Wo, bto_h, bto_l, DD, DD);
    tconv_kernel<<<dim3(FFN_D / 32, 32), 256>>>(Wf1, bf1_h, bf1_l, DD, FFN_D);
    tconv_kernel<<<dim3(32, FFN_D / 32), 256>>>(Wf2, bf2_h, bf2_l, FFN_D, DD);
    tconv_kernel<<<dim3(LORA_P / 32, 32), 256>>>(tw1, btl_h, btl_l, DD, LORA_R);
    pack_bias_kernel<<<QKVS / 256, 256>>>(bq, bk, bv, bqkv);

    // 1. LN1 -> xn (bf16 hi/lo)
    ln_kernel<<<MR, 256>>>(x, n1g, n1b, xnh, xnl);
    // 2. fused QKV projection (HMMA)
    tgemm_kernel<0, 0><<<dim3(QKVS / 128, MR / 128), 256>>>(
        xnh, xnl, btq_h, btq_l, bqkv, nullptr, qkv, nullptr, nullptr, QKVS, DD);
    // 3. LoRA stage 1 (HMMA, padded N=128): tanh(xn @ tw1)
    tgemm_kernel<2, 0><<<dim3(1, MR / 128), 256>>>(
        xnh, xnl, btl_h, btl_l, zero, nullptr, t1, nullptr, nullptr, LORA_P, DD);
    // 4. LoRA stage 2 + decay z
    z_kernel<<<MR, 512>>>(t1, tw2, tb, lb, eta, zr, zi);
    // 5. causal linear attention scan -> y (bf16 hi/lo)
    scan_kernel<<<MB * HH * KSPLIT, 1024>>>(qkv, zr, zi, ybh, ybl);
    // 6. output projection + residual (HMMA) -> x1 fp32
    tgemm_kernel<4, 0><<<dim3(DD / 128, MR / 128), 256>>>(
        ybh, ybl, bto_h, bto_l, bo, x, x1, nullptr, nullptr, DD, DD);
    // 7. LN2 -> h2 (bf16 hi/lo)
    ln_kernel<<<MR, 256>>>(x1, n2g, n2b, h2h, h2l);
    // 8. FFN up + gelu (HMMA) -> mid (bf16 hi/lo)
    tgemm_kernel<3, 1><<<dim3(FFN_D / 128, MR / 128), 256>>>(
        h2h, h2l, bf1_h, bf1_l, bf1, nullptr, nullptr, midh, midl, FFN_D, DD);
    // 9. FFN down + residual -> out (HMMA)
    tgemm_kernel<4, 0><<<dim3(DD / 128, MR / 128), 256>>>(
        midh, midl, bf2_h, bf2_l, bf2, x1, out, nullptr, nullptr, DD, FFN_D);
}